// round 6
// baseline (speedup 1.0000x reference)
#include <cuda_runtime.h>
#include <cuda_bf16.h>
#include <math.h>

// Problem constants (fixed by setup_inputs)
#define NPTS 32768
#define NV   10475
#define NVP  10496          // padded to multiple of 32 (sentinels)
#define NJ   55
#define KNN  6
#define BAT  32             // hot-loop batch (compaction check granularity)
#define CAP  224            // per-thread candidate buffer (local memory)
#define SEPS 1e-3f          // screening slack (>> fp32 rounding skew)

// Scratch (no cudaMalloc allowed).
__device__ int   g_knn_idx[NPTS * KNN];
__device__ float g_knn_d  [NPTS * KNN];

// ---------------------------------------------------------------------------
// Exact-path compaction: process buffered candidate indices with the
// reference-rounded d2 (verified R3/R4/R5):
//   cross = fma(pz,tz, fma(py,ty, fl(px*tx)))
//   d2    = fma(-2, cross, fl(p2 + t2)),  t2 = -2*w (exact, w = -t2/2)
// Buffer is in ascending-v order; strict '<' insert => top_k tie semantics.
// ---------------------------------------------------------------------------
__device__ __forceinline__ void compact_buffer(
    const float4* __restrict__ st, unsigned* lbuf, int& cnt,
    float px, float py, float pz, float p2,
    float bd[KNN], int bi[KNN], float& s_thresh)
{
    for (int j = 0; j < cnt; ++j) {
        int v = lbuf[j];
        float4 t = st[v];
        float t2 = -2.0f * t.w;                       // exact
        float cross = __fmaf_rn(pz, t.z,
                      __fmaf_rn(py, t.y,
                      __fmul_rn(px, t.x)));
        float d2 = __fmaf_rn(-2.0f, cross, __fadd_rn(p2, t2));
        if (d2 < bd[KNN - 1]) {
            bd[KNN - 1] = d2; bi[KNN - 1] = v;
#pragma unroll
            for (int k = KNN - 1; k > 0; --k) {
                if (bd[k] < bd[k - 1]) {              // strict: tie-stable
                    float td_ = bd[k]; bd[k] = bd[k-1]; bd[k-1] = td_;
                    int   ti_ = bi[k]; bi[k] = bi[k-1]; bi[k-1] = ti_;
                }
            }
        }
    }
    cnt = 0;
    // pass screen iff approx-d2 < bd[5] + slack  <=>  s > (p2 - bd[5])/2 - eps
    s_thresh = fmaf(-0.5f, bd[KNN - 1], 0.5f * p2) - SEPS;
}

// ---------------------------------------------------------------------------
// Kernel 1: branch-free screened KNN. One thread = one point, full V.
// Hot loop: s = fma(pz,tz, fma(py,ty, fma(px,tx, -t2/2)))
//           lbuf[cnt] = v; cnt += (s > thresh);      (no branches at all)
// ---------------------------------------------------------------------------
extern "C" __global__ void __launch_bounds__(256, 1)
knn_kernel(const float* __restrict__ pts,      // (N,3)
           const float* __restrict__ tpts)     // (V,3)
{
    extern __shared__ float4 st[];   // NVP float4 = 167936 B

    for (int v = threadIdx.x; v < NVP; v += 256) {
        if (v < NV) {
            float x = tpts[3 * v + 0];
            float y = tpts[3 * v + 1];
            float z = tpts[3 * v + 2];
            float t2 = __fadd_rn(__fadd_rn(__fmul_rn(x, x), __fmul_rn(y, y)),
                                 __fmul_rn(z, z));
            st[v] = make_float4(x, y, z, -0.5f * t2);   // exact halving
        } else {
            st[v] = make_float4(0.0f, 0.0f, 0.0f, -INFINITY);  // sentinel
        }
    }
    __syncthreads();

    const int n = blockIdx.x * 256 + threadIdx.x;

    float px = pts[3 * n + 0];
    float py = pts[3 * n + 1];
    float pz = pts[3 * n + 2];
    float p2 = __fadd_rn(__fadd_rn(__fmul_rn(px, px), __fmul_rn(py, py)),
                         __fmul_rn(pz, pz));

    float bd[KNN];
    int   bi[KNN];
#pragma unroll
    for (int k = 0; k < KNN; ++k) { bd[k] = INFINITY; bi[k] = 0; }

    unsigned lbuf[CAP];              // per-thread local memory buffer
    int   cnt = 0;
    float s_thresh = -INFINITY;      // everything appends until 1st compaction

#pragma unroll 1
    for (int v0 = 0; v0 < NVP; v0 += BAT) {
#pragma unroll
        for (int i = 0; i < BAT; ++i) {
            float4 t = st[v0 + i];
            float s = fmaf(pz, t.z, fmaf(py, t.y, fmaf(px, t.x, t.w)));
            lbuf[cnt] = v0 + i;          // unconditional store (may be junk)
            cnt += (s > s_thresh);       // keep iff passes screen
        }
        if (cnt >= CAP - BAT)            // batch-granular, rarely taken
            compact_buffer(st, lbuf, cnt, px, py, pz, p2, bd, bi, s_thresh);
    }
    compact_buffer(st, lbuf, cnt, px, py, pz, p2, bd, bi, s_thresh);

#pragma unroll
    for (int k = 0; k < KNN; ++k) {
        g_knn_idx[n * KNN + k] = bi[k];
        g_knn_d  [n * KNN + k] = fmaxf(bd[k], 0.0f);  // reference clamp
    }
}

// ---------------------------------------------------------------------------
// Kernel 2: epilogue. One warp = one point. Full reference formula.
// ---------------------------------------------------------------------------
extern "C" __global__ void __launch_bounds__(256)
epilogue_kernel(const float* __restrict__ lbs,   // (V,55)
                const float* __restrict__ vt,    // (V,16)
                float* __restrict__ out)         // [N dist | N*16 transform]
{
    int gwarp = (blockIdx.x * blockDim.x + threadIdx.x) >> 5;
    int lane  = threadIdx.x & 31;

    int   idx[KNN];
    float d[KNN];
#pragma unroll
    for (int k = 0; k < KNN; ++k) {
        idx[k] = g_knn_idx[gwarp * KNN + k];
        d[k]   = g_knn_d  [gwarp * KNN + k];
    }

    const float* w0row = lbs + (long)idx[0] * NJ;
    float w0a = w0row[lane];
    float w0b = (lane < NJ - 32) ? w0row[lane + 32] : 0.0f;

    float conf[KNN];
    conf[0] = 1.0f;
#pragma unroll
    for (int k = 1; k < KNN; ++k) {
        const float* wr = lbs + (long)idx[k] * NJ;
        float a = fabsf(wr[lane] - w0a);
        if (lane < NJ - 32) a += fabsf(wr[lane + 32] - w0b);
#pragma unroll
        for (int off = 16; off >= 1; off >>= 1)
            a += __shfl_xor_sync(0xFFFFFFFFu, a, off);
        conf[k] = (expf(-a * (1.0f / 0.02f)) > 0.9f) ? 1.0f : 0.0f;
    }

    float w[KNN];
    float wsum = 0.0f;
#pragma unroll
    for (int k = 0; k < KNN; ++k) {
        w[k] = expf(-d[k]) * conf[k];
        wsum += w[k];
    }
    float inv = 1.0f / wsum;

    float xd  = 0.0f;
    float acc = 0.0f;
#pragma unroll
    for (int k = 0; k < KNN; ++k) {
        float wk = w[k] * inv;
        xd = fmaf(wk, d[k], xd);
        if (lane < 16)
            acc = fmaf(wk, vt[(long)idx[k] * 16 + lane], acc);
    }

    if (lane == 0) out[gwarp] = xd;
    if (lane < 16) out[NPTS + gwarp * 16 + lane] = acc;
}

// ---------------------------------------------------------------------------
// Launch. Inputs: lbs_weights, verts_transform, points, template_points, K.
// ---------------------------------------------------------------------------
extern "C" void kernel_launch(void* const* d_in, const int* in_sizes, int n_in,
                              void* d_out, int out_size)
{
    const float* lbs  = (const float*)d_in[0];
    const float* vt   = (const float*)d_in[1];
    const float* pts  = (const float*)d_in[2];
    const float* tpts = (const float*)d_in[3];
    float* out = (float*)d_out;

    const int smem_bytes = NVP * (int)sizeof(float4);   // 167936
    cudaFuncSetAttribute(knn_kernel,
                         cudaFuncAttributeMaxDynamicSharedMemorySize,
                         smem_bytes);

    knn_kernel<<<NPTS / 256, 256, smem_bytes>>>(pts, tpts);
    epilogue_kernel<<<(NPTS * 32) / 256, 256>>>(lbs, vt, out);
}

// round 7
// speedup vs baseline: 1.7043x; 1.7043x over previous
#include <cuda_runtime.h>
#include <cuda_bf16.h>
#include <math.h>

// Problem constants (fixed by setup_inputs)
#define NPTS 32768
#define NV   10475
#define NJ   55
#define KNN  6

// Spatial grid
#define GDIM  64
#define NCELL (GDIM * GDIM * GDIM)      // 262144
#define GL    10.0f                     // grid covers [-10, 10]^3
#define GH    0.3125f                   // cell size = 20/64
#define GINV  3.2f                      // 1/GH
#define P2CUT 7.84f                     // |p|^2 > 2.8^2 -> cooperative brute

typedef unsigned long long u64;
#define KSENT 0xFFFFFFFFFFFFFFFFull

// Scratch (no cudaMalloc allowed).
__device__ int    g_counts[NCELL];
__device__ int    g_start [NCELL + 1];
__device__ int    g_cursor[NCELL];
__device__ float4 g_sorted[NV];          // {x, y, z, orig_idx_bits}
__device__ int    g_knn_idx[NPTS * KNN];
__device__ float  g_knn_d  [NPTS * KNN];

// ---------------------------------------------------------------------------
__device__ __forceinline__ int cell_of(float x, float y, float z) {
    int cx = min(GDIM - 1, max(0, (int)((x + GL) * GINV)));
    int cy = min(GDIM - 1, max(0, (int)((y + GL) * GINV)));
    int cz = min(GDIM - 1, max(0, (int)((z + GL) * GINV)));
    return (cz * GDIM + cy) * GDIM + cx;
}

// Exact reference-rounded d2 (verified R3-R6), clamped BEFORE selection
// like the reference, packed into a (d2, orig_idx) sortable key.
__device__ __forceinline__ u64 cand_key(float4 t, float px, float py, float pz,
                                        float p2) {
    float t2 = __fadd_rn(__fadd_rn(__fmul_rn(t.x, t.x), __fmul_rn(t.y, t.y)),
                         __fmul_rn(t.z, t.z));
    float cross = __fmaf_rn(pz, t.z, __fmaf_rn(py, t.y, __fmul_rn(px, t.x)));
    float d2 = fmaxf(__fmaf_rn(-2.0f, cross, __fadd_rn(p2, t2)), 0.0f);
    return ((u64)__float_as_uint(d2) << 32) | (u64)__float_as_uint(t.w);
}

__device__ __forceinline__ void key_insert(u64* K, u64 key) {
    if (key < K[KNN - 1]) {
        K[KNN - 1] = key;
#pragma unroll
        for (int k = KNN - 1; k > 0; --k)
            if (K[k] < K[k - 1]) { u64 t = K[k]; K[k] = K[k - 1]; K[k - 1] = t; }
    }
}

// ---------------------------------------------------------------------------
// Prep kernels
// ---------------------------------------------------------------------------
extern "C" __global__ void k_zero() {
    int i = blockIdx.x * blockDim.x + threadIdx.x;
    for (; i < NCELL; i += gridDim.x * blockDim.x) g_counts[i] = 0;
}

extern "C" __global__ void k_hist(const float* __restrict__ tpts) {
    int v = blockIdx.x * blockDim.x + threadIdx.x;
    if (v >= NV) return;
    atomicAdd(&g_counts[cell_of(tpts[3*v], tpts[3*v+1], tpts[3*v+2])], 1);
}

extern "C" __global__ void __launch_bounds__(1024) k_scan() {
    __shared__ int sA[1024], sB[1024];
    const int t = threadIdx.x;
    const int C = NCELL / 1024;          // 256 cells per thread
    int sum = 0;
    for (int i = 0; i < C; ++i) sum += g_counts[t * C + i];
    sA[t] = sum; __syncthreads();
    int *src = sA, *dst = sB;
    for (int off = 1; off < 1024; off <<= 1) {
        int v = src[t] + ((t >= off) ? src[t - off] : 0);
        dst[t] = v; __syncthreads();
        int* tmp = src; src = dst; dst = tmp;
    }
    int run = src[t] - sum;              // exclusive base of this chunk
    for (int i = 0; i < C; ++i) {
        int id = t * C + i;
        g_start[id] = run; g_cursor[id] = run;
        run += g_counts[id];
    }
    if (t == 1023) g_start[NCELL] = run; // == NV
}

extern "C" __global__ void k_scatter(const float* __restrict__ tpts) {
    int v = blockIdx.x * blockDim.x + threadIdx.x;
    if (v >= NV) return;
    float x = tpts[3*v], y = tpts[3*v+1], z = tpts[3*v+2];
    int pos = atomicAdd(&g_cursor[cell_of(x, y, z)], 1);
    g_sorted[pos] = make_float4(x, y, z, __uint_as_float((unsigned)v));
}

// ---------------------------------------------------------------------------
// Kernel B: grid KNN. Sorted templates in smem; ring expansion per lane with
// exact-rounded keyed selection; warp-cooperative brute for far points.
// ---------------------------------------------------------------------------
extern "C" __global__ void __launch_bounds__(256, 1)
k_knn(const float* __restrict__ pts)
{
    extern __shared__ float4 st[];       // NV float4 = 167600 B

    for (int i = threadIdx.x; i < NV; i += 256) st[i] = g_sorted[i];
    __syncthreads();

    const int n = blockIdx.x * 256 + threadIdx.x;
    const int lane = threadIdx.x & 31;

    float px = pts[3*n], py = pts[3*n+1], pz = pts[3*n+2];
    float p2 = __fadd_rn(__fadd_rn(__fmul_rn(px,px), __fmul_rn(py,py)),
                         __fmul_rn(pz,pz));

    u64 K[KNN];
#pragma unroll
    for (int k = 0; k < KNN; ++k) K[k] = KSENT;

    bool far = (p2 > P2CUT);

    if (!far) {
        int cx = min(GDIM-1, max(0, (int)((px + GL) * GINV)));
        int cy = min(GDIM-1, max(0, (int)((py + GL) * GINV)));
        int cz = min(GDIM-1, max(0, (int)((pz + GL) * GINV)));

        for (int r = 0; r < GDIM; ++r) {
            int z0 = max(cz - r, 0), z1 = min(cz + r, GDIM - 1);
            int y0 = max(cy - r, 0), y1 = min(cy + r, GDIM - 1);
            for (int zz = z0; zz <= z1; ++zz) {
                bool ze = (zz == cz - r) || (zz == cz + r);
                for (int yy = y0; yy <= y1; ++yy) {
                    bool ye = (yy == cy - r) || (yy == cy + r);
                    int xa = cx - r, xb = cx + r;
                    if (ze || ye) {
                        int x0 = max(xa, 0), x1 = min(xb, GDIM - 1);
                        int cb = (zz * GDIM + yy) * GDIM;
                        for (int xx = x0; xx <= x1; ++xx) {
                            int c = cb + xx;
                            int s = g_start[c], e = g_start[c + 1];
                            for (int j = s; j < e; ++j)
                                key_insert(K, cand_key(st[j], px, py, pz, p2));
                        }
                    } else {
                        // interior row: only the two x-faces
                        int cb = (zz * GDIM + yy) * GDIM;
                        if (xa >= 0) {
                            int c = cb + xa;
                            int s = g_start[c], e = g_start[c + 1];
                            for (int j = s; j < e; ++j)
                                key_insert(K, cand_key(st[j], px, py, pz, p2));
                        }
                        if (xb <= GDIM - 1 && r > 0) {
                            int c = cb + xb;
                            int s = g_start[c], e = g_start[c + 1];
                            for (int j = s; j < e; ++j)
                                key_insert(K, cand_key(st[j], px, py, pz, p2));
                        }
                    }
                }
            }
            if (K[KNN - 1] != KSENT) {
                float d5  = __uint_as_float((unsigned)(K[KNN - 1] >> 32));
                float rad = (float)r * GH;
                if (d5 < 0.999f * rad * rad) break;   // all unscanned are farther
            }
        }
    }

    // Warp-cooperative brute for far lanes.
    __syncwarp();
    unsigned fm = __ballot_sync(0xFFFFFFFFu, far);
    while (fm) {
        int f = __ffs(fm) - 1; fm &= fm - 1;
        float qx = __shfl_sync(0xFFFFFFFFu, px, f);
        float qy = __shfl_sync(0xFFFFFFFFu, py, f);
        float qz = __shfl_sync(0xFFFFFFFFu, pz, f);
        float q2 = __shfl_sync(0xFFFFFFFFu, p2, f);

        u64 T[KNN];
#pragma unroll
        for (int k = 0; k < KNN; ++k) T[k] = KSENT;
        for (int j = lane; j < NV; j += 32)
            key_insert(T, cand_key(st[j], qx, qy, qz, q2));

        u64 L[8];
#pragma unroll
        for (int k = 0; k < KNN; ++k) L[k] = T[k];
        L[6] = KSENT; L[7] = KSENT;

        // 5-round pairwise bitonic merge of sorted-8 lists across the warp
#pragma unroll
        for (int off = 1; off < 32; off <<= 1) {
            u64 B[8];
#pragma unroll
            for (int k = 0; k < 8; ++k)
                B[k] = __shfl_xor_sync(0xFFFFFFFFu, L[k], off);
            u64 M[8];
#pragma unroll
            for (int k = 0; k < 8; ++k)
                M[k] = (L[k] < B[7 - k]) ? L[k] : B[7 - k];   // lowest 8, bitonic
            // bitonic clean (distances 4, 2, 1) -> ascending
#pragma unroll
            for (int k = 0; k < 4; ++k)
                if (M[k] > M[k+4]) { u64 t = M[k]; M[k] = M[k+4]; M[k+4] = t; }
#pragma unroll
            for (int k = 0; k < 2; ++k) {
                if (M[k]   > M[k+2]) { u64 t = M[k];   M[k]   = M[k+2]; M[k+2] = t; }
                if (M[k+4] > M[k+6]) { u64 t = M[k+4]; M[k+4] = M[k+6]; M[k+6] = t; }
            }
#pragma unroll
            for (int k = 0; k < 8; k += 2)
                if (M[k] > M[k+1]) { u64 t = M[k]; M[k] = M[k+1]; M[k+1] = t; }
#pragma unroll
            for (int k = 0; k < 8; ++k) L[k] = M[k];
        }
        if (lane == f) {
#pragma unroll
            for (int k = 0; k < KNN; ++k) K[k] = L[k];
        }
    }

#pragma unroll
    for (int k = 0; k < KNN; ++k) {
        g_knn_idx[n * KNN + k] = (int)(unsigned)(K[k] & 0xFFFFFFFFull);
        g_knn_d  [n * KNN + k] = __uint_as_float((unsigned)(K[k] >> 32));
    }
}

// ---------------------------------------------------------------------------
// Epilogue (unchanged, measured 17us). One warp = one point.
// ---------------------------------------------------------------------------
extern "C" __global__ void __launch_bounds__(256)
epilogue_kernel(const float* __restrict__ lbs,   // (V,55)
                const float* __restrict__ vt,    // (V,16)
                float* __restrict__ out)         // [N dist | N*16 transform]
{
    int gwarp = (blockIdx.x * blockDim.x + threadIdx.x) >> 5;
    int lane  = threadIdx.x & 31;

    int   idx[KNN];
    float d[KNN];
#pragma unroll
    for (int k = 0; k < KNN; ++k) {
        idx[k] = g_knn_idx[gwarp * KNN + k];
        d[k]   = g_knn_d  [gwarp * KNN + k];
    }

    const float* w0row = lbs + (long)idx[0] * NJ;
    float w0a = w0row[lane];
    float w0b = (lane < NJ - 32) ? w0row[lane + 32] : 0.0f;

    float conf[KNN];
    conf[0] = 1.0f;
#pragma unroll
    for (int k = 1; k < KNN; ++k) {
        const float* wr = lbs + (long)idx[k] * NJ;
        float a = fabsf(wr[lane] - w0a);
        if (lane < NJ - 32) a += fabsf(wr[lane + 32] - w0b);
#pragma unroll
        for (int off = 16; off >= 1; off >>= 1)
            a += __shfl_xor_sync(0xFFFFFFFFu, a, off);
        conf[k] = (expf(-a * (1.0f / 0.02f)) > 0.9f) ? 1.0f : 0.0f;
    }

    float w[KNN];
    float wsum = 0.0f;
#pragma unroll
    for (int k = 0; k < KNN; ++k) {
        w[k] = expf(-d[k]) * conf[k];
        wsum += w[k];
    }
    float inv = 1.0f / wsum;

    float xd  = 0.0f;
    float acc = 0.0f;
#pragma unroll
    for (int k = 0; k < KNN; ++k) {
        float wk = w[k] * inv;
        xd = fmaf(wk, d[k], xd);
        if (lane < 16)
            acc = fmaf(wk, vt[(long)idx[k] * 16 + lane], acc);
    }

    if (lane == 0) out[gwarp] = xd;
    if (lane < 16) out[NPTS + gwarp * 16 + lane] = acc;
}

// ---------------------------------------------------------------------------
// Launch. Inputs: lbs_weights, verts_transform, points, template_points, K.
// ---------------------------------------------------------------------------
extern "C" void kernel_launch(void* const* d_in, const int* in_sizes, int n_in,
                              void* d_out, int out_size)
{
    const float* lbs  = (const float*)d_in[0];
    const float* vt   = (const float*)d_in[1];
    const float* pts  = (const float*)d_in[2];
    const float* tpts = (const float*)d_in[3];
    float* out = (float*)d_out;

    const int smem_bytes = NV * (int)sizeof(float4);   // 167600
    cudaFuncSetAttribute(k_knn,
                         cudaFuncAttributeMaxDynamicSharedMemorySize,
                         smem_bytes);

    k_zero<<<256, 256>>>();
    k_hist<<<(NV + 255) / 256, 256>>>(tpts);
    k_scan<<<1, 1024>>>();
    k_scatter<<<(NV + 255) / 256, 256>>>(tpts);
    k_knn<<<NPTS / 256, 256, smem_bytes>>>(pts);
    epilogue_kernel<<<(NPTS * 32) / 256, 256>>>(lbs, vt, out);
}